// round 6
// baseline (speedup 1.0000x reference)
#include <cuda_runtime.h>
#include <cuda_bf16.h>
#include <math.h>

// GaussianMixture: B=8, N=131072, K=4, F=20, 5 EM iters, REG_COVAR=1e-4.
// Quad per point; lane t loads features f ≡ t (mod 4). Math packed f32x2
// across components. E-step constants in SMEM (kills reg spills); 2-point
// software pipelining per loop iteration. M-step fused into next accum.

#define BB 8
#define NPTS 131072
#define KC 4
#define FDIM 20
#define NSL 5
#define CTAS_PER_B 37
#define THREADS 256
#define TEAMS_PER_CTA (THREADS/4)                 // 64
#define TEAM_STRIDE (CTAS_PER_B*TEAMS_PER_CTA)    // 2368
#define LOG2PI 1.8378770664093454f

#define RESP_OFF   0
#define LP_OFF     (BB*NPTS*KC)
#define M_OFF      (2*BB*NPTS*KC)
#define COV_OFF    (M_OFF + BB*KC*FDIM)
#define PRIOR_OFF  (COV_OFF + BB*KC*FDIM*FDIM)

typedef unsigned long long u64;

__device__ __forceinline__ u64 pack2(float lo, float hi) {
    u64 d; asm("mov.b64 %0, {%1,%2};" : "=l"(d) : "f"(lo), "f"(hi)); return d;
}
__device__ __forceinline__ void unpack2(u64 v, float& lo, float& hi) {
    asm("mov.b64 {%0,%1}, %2;" : "=f"(lo), "=f"(hi) : "l"(v));
}
__device__ __forceinline__ u64 fma2(u64 a, u64 b, u64 c) {
    u64 d; asm("fma.rn.f32x2 %0, %1, %2, %3;" : "=l"(d) : "l"(a), "l"(b), "l"(c)); return d;
}
__device__ __forceinline__ u64 mul2(u64 a, u64 b) {
    u64 d; asm("mul.rn.f32x2 %0, %1, %2;" : "=l"(d) : "l"(a), "l"(b)); return d;
}
__device__ __forceinline__ u64 add2(u64 a, u64 b) {
    u64 d; asm("add.rn.f32x2 %0, %1, %2;" : "=l"(d) : "l"(a), "l"(b)); return d;
}
__device__ __forceinline__ u64 shfl_xor64(u64 v, int m) {
    return __shfl_xor_sync(0xffffffffu, v, m);
}

// Double-buffered sums: slot it holds results of iteration it.
__device__ float g_sums[5][BB][256];   // zero at load; gmm_final re-zeroes

// ---------------------------------------------------------------------------
__global__ void __launch_bounds__(THREADS, 2)
gmm_accum(const float* __restrict__ data,
          const float* __restrict__ means,
          const float* __restrict__ covv,
          float* __restrict__ out_resp,
          float* __restrict__ out_lp,
          int it, int write_out)
{
    const int b    = blockIdx.y;
    const int tid  = threadIdx.x;
    const int lane = tid & 31;
    const int t    = lane & 3;
    const int team_g = blockIdx.x * TEAMS_PER_CTA + (tid >> 2);

    // packed e-step constants live in SMEM: [t][{c1A,c1B,c2A,c2B}][i]
    __shared__ u64 s_cst[4][4][NSL];
    __shared__ float s_acc[256];

    float Ck;
    {   // ---- prologue: fused M-step of previous iteration ----
        float c1s[KC][NSL], c2s[KC][NSL], ldp[KC];
        #pragma unroll
        for (int jj = 0; jj < KC; jj++) {
            const int c = t ^ jj;
            ldp[jj] = 0.f;
            #pragma unroll
            for (int i = 0; i < NSL; i++) {
                const int f = t + 4*i;
                float mu, var;
                if (it == 0) {
                    mu  = means[(b*KC + c)*FDIM + f];
                    var = covv [(b*KC + c)*FDIM + f];
                } else {
                    const float* s = g_sums[it-1][b];
                    const float S1c = s[240 + c], S2c = s[244 + c];
                    const float sx   = s[        c*FDIM + f];
                    const float s2x  = s[ 80 +   c*FDIM + f];
                    const float s2xx = s[160 +   c*FDIM + f];
                    mu  = sx / S1c;
                    var = (s2xx - 2.f*mu*s2x + mu*mu*S2c) / S1c;
                    var = fmaxf(var, 1e-4f);
                }
                const float iv = 1.f / var;
                c2s[jj][i] = iv;
                c1s[jj][i] = -2.f*mu*iv;
                ldp[jj] += __logf(var) + iv*mu*mu;
            }
        }
        if (tid < 4) {  // tid == t: store packed constants once per CTA
            #pragma unroll
            for (int i = 0; i < NSL; i++) {
                s_cst[tid][0][i] = pack2(c1s[0][i], c1s[1][i]);
                s_cst[tid][1][i] = pack2(c1s[2][i], c1s[3][i]);
                s_cst[tid][2][i] = pack2(c2s[0][i], c2s[1][i]);
                s_cst[tid][3][i] = pack2(c2s[2][i], c2s[3][i]);
            }
        }
        u64 sld = add2(pack2(ldp[0], ldp[1]), shfl_xor64(pack2(ldp[2], ldp[3]), 2));
        float llo, lhi; unpack2(sld, llo, lhi);
        const float ld_self = llo + __shfl_xor_sync(0xffffffffu, lhi, 1);
        Ck = -0.5f*(FDIM*LOG2PI + ld_self);

        for (int i = tid; i < 256; i += THREADS) s_acc[i] = 0.f;
        __syncthreads();
    }
    const u64* __restrict__ cst = &s_cst[t][0][0];   // 20 u64: c1A,c1B,c2A,c2B

    // k-packed accumulators
    u64 SxA[NSL], SxB[NSL], S2xA[NSL], S2xB[NSL], S2xxA[NSL], S2xxB[NSL];
    float S1 = 0.f, S2 = 0.f;
    #pragma unroll
    for (int i = 0; i < NSL; i++) {
        SxA[i]=0; SxB[i]=0; S2xA[i]=0; S2xB[i]=0; S2xxA[i]=0; S2xxB[i]=0;
    }

    const float* __restrict__ xptr = data + (size_t)b*NPTS*FDIM + t;
    float* __restrict__ orp = out_resp + (size_t)b*NPTS*KC + t;
    float* __restrict__ olp = out_lp   + (size_t)b*NPTS*KC + t;

    auto body = [&](const float xin[NSL], int p, bool valid) {
        float x[NSL];
        #pragma unroll
        for (int i = 0; i < NSL; i++) x[i] = valid ? xin[i] : 0.f;

        u64 aA = 0, aB = 0;
        #pragma unroll
        for (int i = 0; i < NSL; i++) {
            const float xf = x[i], xxf = xf*xf;
            const u64 xp  = pack2(xf,  xf);
            const u64 xxp = pack2(xxf, xxf);
            aA = fma2(cst[2*NSL+i], xxp, aA);
            aA = fma2(cst[      i], xp,  aA);
            aB = fma2(cst[3*NSL+i], xxp, aB);
            aB = fma2(cst[  NSL+i], xp,  aB);
        }
        u64 sA = add2(aA, shfl_xor64(aB, 2));
        float slo, shi; unpack2(sA, slo, shi);
        const float a_self = slo + __shfl_xor_sync(0xffffffffu, shi, 1);

        const float lp = fmaf(-0.5f, a_self, Ck);
        const float pr = __expf(lp) + 1e-8f;
        const float p1 = __shfl_xor_sync(0xffffffffu, pr, 1);
        const u64 prA = pack2(pr, p1);
        const u64 prB = shfl_xor64(prA, 2);
        float q2, q3; unpack2(prB, q2, q3);
        const float s = (pr + p1) + (q2 + q3);
        const float rinv = __fdividef(1.f, s);
        const u64 rinv2 = pack2(rinv, rinv);
        const u64 rA = mul2(prA, rinv2), rB = mul2(prB, rinv2);
        const u64 r2A = mul2(rA, rA),    r2B = mul2(rB, rB);
        float r0, r1f; unpack2(rA, r0, r1f);
        if (valid) { S1 += r0; S2 += r0*r0; }

        #pragma unroll
        for (int i = 0; i < NSL; i++) {
            const float xf = x[i], xxf = xf*xf;
            const u64 xp  = pack2(xf,  xf);
            const u64 xxp = pack2(xxf, xxf);
            SxA[i]   = fma2(rA,  xp,  SxA[i]);
            SxB[i]   = fma2(rB,  xp,  SxB[i]);
            S2xA[i]  = fma2(r2A, xp,  S2xA[i]);
            S2xB[i]  = fma2(r2B, xp,  S2xB[i]);
            S2xxA[i] = fma2(r2A, xxp, S2xxA[i]);
            S2xxB[i] = fma2(r2B, xxp, S2xxB[i]);
        }
        if (write_out && valid) {
            orp[(size_t)p*KC] = r0;
            olp[(size_t)p*KC] = lp;
        }
    };

    // ---- main loop: 2 points per iteration, pair-ahead prefetch ----
    const int S = TEAM_STRIDE;
    int p0 = team_g;
    float x0[NSL], x1[NSL], x0n[NSL], x1n[NSL];
    #pragma unroll
    for (int i = 0; i < NSL; i++) {
        x0[i] = __ldg(xptr + (size_t)p0*FDIM + 4*i);
        x1[i] = __ldg(xptr + (size_t)(p0+S)*FDIM + 4*i);
    }

    #pragma unroll 1
    for (int m = 0; m < 27; m++) {                 // pairs 0..26 fully valid
        const int pn0 = p0 + 2*S;
        const int pn1 = pn0 + S;
        const int pn1c = (pn1 < NPTS) ? pn1 : 0;
        #pragma unroll
        for (int i = 0; i < NSL; i++) {
            x0n[i] = __ldg(xptr + (size_t)pn0*FDIM + 4*i);
            x1n[i] = __ldg(xptr + (size_t)pn1c*FDIM + 4*i);
        }
        body(x0, p0,     true);
        body(x1, p0 + S, true);
        #pragma unroll
        for (int i = 0; i < NSL; i++) { x0[i] = x0n[i]; x1[i] = x1n[i]; }
        p0 = pn0;
    }
    // last pair: point 54 valid, point 55 maybe not
    body(x0, p0, true);
    body(x1, p0 + S, (p0 + S) < NPTS);

    // ---- cross-team warp reduce ----
    #pragma unroll
    for (int off = 4; off < 32; off <<= 1) {
        #pragma unroll
        for (int i = 0; i < NSL; i++) {
            SxA[i]   = add2(SxA[i],   shfl_xor64(SxA[i],   off));
            SxB[i]   = add2(SxB[i],   shfl_xor64(SxB[i],   off));
            S2xA[i]  = add2(S2xA[i],  shfl_xor64(S2xA[i],  off));
            S2xB[i]  = add2(S2xB[i],  shfl_xor64(S2xB[i],  off));
            S2xxA[i] = add2(S2xxA[i], shfl_xor64(S2xxA[i], off));
            S2xxB[i] = add2(S2xxB[i], shfl_xor64(S2xxB[i], off));
        }
        S1 += __shfl_xor_sync(0xffffffffu, S1, off);
        S2 += __shfl_xor_sync(0xffffffffu, S2, off);
    }

    if (lane < 4) {   // lane == t
        #pragma unroll
        for (int i = 0; i < NSL; i++) {
            const int f = t + 4*i;
            float lo, hi;
            unpack2(SxA[i], lo, hi);
            atomicAdd(&s_acc[(t  )*FDIM + f], lo);
            atomicAdd(&s_acc[(t^1)*FDIM + f], hi);
            unpack2(SxB[i], lo, hi);
            atomicAdd(&s_acc[(t^2)*FDIM + f], lo);
            atomicAdd(&s_acc[(t^3)*FDIM + f], hi);
            unpack2(S2xA[i], lo, hi);
            atomicAdd(&s_acc[80 + (t  )*FDIM + f], lo);
            atomicAdd(&s_acc[80 + (t^1)*FDIM + f], hi);
            unpack2(S2xB[i], lo, hi);
            atomicAdd(&s_acc[80 + (t^2)*FDIM + f], lo);
            atomicAdd(&s_acc[80 + (t^3)*FDIM + f], hi);
            unpack2(S2xxA[i], lo, hi);
            atomicAdd(&s_acc[160 + (t  )*FDIM + f], lo);
            atomicAdd(&s_acc[160 + (t^1)*FDIM + f], hi);
            unpack2(S2xxB[i], lo, hi);
            atomicAdd(&s_acc[160 + (t^2)*FDIM + f], lo);
            atomicAdd(&s_acc[160 + (t^3)*FDIM + f], hi);
        }
        atomicAdd(&s_acc[240 + t], S1);
        atomicAdd(&s_acc[244 + t], S2);
    }
    __syncthreads();
    for (int i = tid; i < 248; i += THREADS)
        atomicAdd(&g_sums[it][b][i], s_acc[i]);
}

// ---------------------------------------------------------------------------
__global__ void gmm_final(float* __restrict__ out_m,
                          float* __restrict__ out_cov,
                          float* __restrict__ out_prior)
{
    const int b = blockIdx.x;
    const int k = threadIdx.x >> 5;
    const int lane = threadIdx.x & 31;
    const float* s = g_sums[4][b];

    const float S1 = s[240 + k];
    const float S2 = s[244 + k];
    float mu = 0.f, var = 1.f;
    if (lane < FDIM) {
        const float sx   = s[        k*FDIM + lane];
        const float s2x  = s[ 80 +   k*FDIM + lane];
        const float s2xx = s[160 +   k*FDIM + lane];
        mu  = sx / S1;
        var = (s2xx - 2.f*mu*s2x + mu*mu*S2) / S1;
        var = fmaxf(var, 1e-4f);
        out_m[(b*KC + k)*FDIM + lane] = mu;
    }
    if (lane == 0) out_prior[b*KC + k] = S1;
    #pragma unroll
    for (int i = 0; i < FDIM; i++) {
        const float vi = __shfl_sync(0xffffffffu, var, i);
        if (lane < FDIM)
            out_cov[(((size_t)(b*KC + k))*FDIM + i)*FDIM + lane] =
                (lane == i) ? vi : 0.f;
    }

    __syncthreads();
    for (int itt = 0; itt < 5; itt++)
        for (int i = threadIdx.x; i < 256; i += blockDim.x)
            g_sums[itt][b][i] = 0.f;
}

// ---------------------------------------------------------------------------
extern "C" void kernel_launch(void* const* d_in, const int* in_sizes, int n_in,
                              void* d_out, int out_size)
{
    (void)in_sizes; (void)n_in; (void)out_size;
    const float* data  = (const float*)d_in[0];
    const float* means = (const float*)d_in[1];
    const float* cov   = (const float*)d_in[2];
    float* out = (float*)d_out;

    float* out_resp  = out + RESP_OFF;
    float* out_lp    = out + LP_OFF;
    float* out_m     = out + M_OFF;
    float* out_cov   = out + COV_OFF;
    float* out_prior = out + PRIOR_OFF;

    for (int it = 0; it < 5; it++)
        gmm_accum<<<dim3(CTAS_PER_B, BB), THREADS>>>(
            data, means, cov, out_resp, out_lp, it, (it == 4) ? 1 : 0);
    gmm_final<<<BB, 128>>>(out_m, out_cov, out_prior);
}